// round 16
// baseline (speedup 1.0000x reference)
#include <cuda_runtime.h>
#include <cuda_fp16.h>
#include <math.h>
#include <stdint.h>

#define BB 2
#define TT 2048
#define EE 1024
#define HH 16
#define DD 64
#define BT (BB*TT)            // 4096
#define BIAS_LEN (2*TT-1)     // 4095

// Scratch (device globals)
__device__ float g_gate[BB*HH*TT];
__device__ float g_bias[BIAS_LEN*HH];
__device__ __half g_qh[BB*HH*TT*DD];
__device__ __half g_kh[BB*HH*TT*DD];
__device__ __half g_vh[BB*HH*TT*DD];
__device__ __half g_xhi[BT*EE], g_xlo[BT*EE];
__device__ __half g_whi[4*EE*EE];
__device__ __half g_chi[BT*EE], g_clo[BT*EE];

// ===========================================================================
// helpers
// ===========================================================================
__device__ __forceinline__ uint32_t smem_u32(const void* p) {
    uint32_t a;
    asm("{ .reg .u64 t; cvta.to.shared.u64 t, %1; cvt.u32.u64 %0, t; }" : "=r"(a) : "l"(p));
    return a;
}
__device__ __forceinline__ void cp16(uint32_t dst, const void* src) {
    asm volatile("cp.async.ca.shared.global [%0], [%1], 16;" :: "r"(dst), "l"(src));
}
#define CP_COMMIT() asm volatile("cp.async.commit_group;" ::: "memory")
#define CP_WAIT1()  asm volatile("cp.async.wait_group 1;" ::: "memory")
#define CP_WAIT0()  asm volatile("cp.async.wait_group 0;" ::: "memory")

__device__ __forceinline__ void hmma16816(float c[4],
                                          uint32_t a0, uint32_t a1, uint32_t a2, uint32_t a3,
                                          uint32_t b0, uint32_t b1)
{
    asm volatile(
        "mma.sync.aligned.m16n8k16.row.col.f32.f16.f16.f32 "
        "{%0,%1,%2,%3}, {%4,%5,%6,%7}, {%8,%9}, {%0,%1,%2,%3};"
        : "+f"(c[0]), "+f"(c[1]), "+f"(c[2]), "+f"(c[3])
        : "r"(a0), "r"(a1), "r"(a2), "r"(a3), "r"(b0), "r"(b1));
}
// FMA-pipe exp (no MUFU); args <= 0 (online-max softmax)
__device__ __forceinline__ float fexp(float x) {
    x = fmaxf(x, -80.0f);
    float z = fmaf(x, 1.4426950408889634f, 12582912.0f);
    int n = __float_as_int(z) - 0x4B400000;
    float r = z - 12582912.0f;
    float f = fmaf(r, -0.6931471805599453f, x);
    float p = fmaf(f, 0.008333333f, 0.041666666f);
    p = fmaf(f, p, 0.16666667f);
    p = fmaf(f, p, 0.5f);
    p = fmaf(f, p, 1.0f);
    p = fmaf(f, p, 1.0f);
    return __int_as_float(__float_as_int(p) + (n << 23));
}
__device__ __forceinline__ uint32_t packh2(float a, float b) {
    __half2 t = __floats2half2_rn(a, b);
    return *(uint32_t*)&t;
}
__device__ __forceinline__ void splith2(float a, float b, uint32_t& hi, uint32_t& lo) {
    __half ha = __float2half_rn(a), hb = __float2half_rn(b);
    __half2 t{ha, hb};
    hi = *(uint32_t*)&t;
    lo = packh2(a - __half2float(ha), b - __half2float(hb));
}

// ===========================================================================
// Fused prep: conv_x | conv_w (hi only) | gate | bias_table
// ===========================================================================
#define PREP_CX 4096
#define PREP_CW 4096
#define PREP_GT 256
#define PREP_BT 16
#define PREP_BLOCKS (PREP_CX + PREP_CW + PREP_GT + PREP_BT)

__global__ __launch_bounds__(256) void prep_kernel(
    const float* __restrict__ hidden,
    const float* __restrict__ w0, const float* __restrict__ w1,
    const float* __restrict__ w2, const float* __restrict__ w3,
    const float* __restrict__ gru_w, const float* __restrict__ gru_b,
    const float* __restrict__ gru_const,
    const float* __restrict__ rel_embed)
{
    int bx = blockIdx.x;
    int tid = threadIdx.x;

    if (bx < PREP_CX) {
        int i = (bx * 256 + tid) * 4;
        float4 v = *(const float4*)&hidden[i];
        uint32_t h01, l01, h23, l23;
        splith2(v.x, v.y, h01, l01);
        splith2(v.z, v.w, h23, l23);
        *(uint2*)&g_xhi[i] = make_uint2(h01, h23);
        *(uint2*)&g_xlo[i] = make_uint2(l01, l23);
        return;
    }
    bx -= PREP_CX;
    if (bx < PREP_CW) {
        int i = (bx * 256 + tid) * 4;
        int sel = i >> 20;
        const float* src = sel==0 ? w0 : sel==1 ? w1 : sel==2 ? w2 : w3;
        float4 v = *(const float4*)&src[i & ((1<<20)-1)];
        uint32_t h01 = packh2(v.x, v.y);
        uint32_t h23 = packh2(v.z, v.w);
        *(uint2*)&g_whi[i] = make_uint2(h01, h23);
        return;
    }
    bx -= PREP_CW;
    if (bx < PREP_GT) {
        __shared__ float sw[8*DD];
        __shared__ float sb[8];
        __shared__ float scs[HH];
        for (int i = tid; i < 8*DD; i += 256) sw[i] = gru_w[i];
        if (tid < 8)  sb[tid] = gru_b[tid];
        if (tid < HH) scs[tid] = gru_const[tid];
        __syncthreads();

        int i = bx * 256 + tid;       // full 65536 coverage
        int h  = i % HH;
        int bt = i / HH;
        const float* x = hidden + (size_t)bt*EE + h*DD;
        float p[8];
        #pragma unroll
        for (int j = 0; j < 8; j++) p[j] = sb[j];
        #pragma unroll
        for (int d = 0; d < DD; d += 4) {
            float4 xv = *(const float4*)&x[d];
            #pragma unroll
            for (int j = 0; j < 8; j++) {
                p[j] += xv.x*sw[j*DD+d] + xv.y*sw[j*DD+d+1]
                      + xv.z*sw[j*DD+d+2] + xv.w*sw[j*DD+d+3];
            }
        }
        float pa = p[0]+p[1]+p[2]+p[3];
        float pb = p[4]+p[5]+p[6]+p[7];
        float ga = 1.0f/(1.0f + __expf(-pa));
        float gb = 1.0f/(1.0f + __expf(-pb));
        float gout = ga*(gb*scs[h] - 1.0f) + 2.0f;
        int b = bt / TT, t = bt % TT;
        g_gate[(b*HH + h)*TT + t] = gout;
        return;
    }
    bx -= PREP_GT;
    {
        int idx = bx * 256 + tid;
        if (idx >= BIAS_LEN) return;
        int delta = idx - (TT - 1);
        const int nb = 160;
        const int max_exact = 80;
        int rb = (delta > 0) ? nb : 0;
        int rel = abs(delta);
        int v;
        if (rel < max_exact) {
            v = rel;
        } else {
            float rf = (float)(rel < 1 ? 1 : rel);
            float large = logf(rf * (1.0f/80.0f)) * (float)(80.0 / 2.302585092994645684);
            int li = (int)((float)max_exact + large);
            v = li < (nb - 1) ? li : (nb - 1);
        }
        // NOTE: constant above must match reference exactly; re-derive:
        // log(800/80) = log(10) = 2.302585092994046
        bucket_store:
        {
            int delta2 = idx - (TT - 1);
            int rb2 = (delta2 > 0) ? nb : 0;
            int rel2 = abs(delta2);
            int v2;
            if (rel2 < max_exact) {
                v2 = rel2;
            } else {
                float rf2 = (float)(rel2 < 1 ? 1 : rel2);
                float large2 = logf(rf2 * (1.0f/80.0f)) * (float)(80.0 / 2.302585092994045684);
                int li2 = (int)((float)max_exact + large2);
                v2 = li2 < (nb - 1) ? li2 : (nb - 1);
            }
            int bucket = rb2 + v2;
            #pragma unroll
            for (int h = 0; h < HH; h++)
                g_bias[idx*HH + h] = rel_embed[bucket*HH + h];
        }
    }
}

// ===========================================================================
// HMMA GEMM, fp16 2-pass (A hi/lo, W fp16), cp.async 2-stage, KC=32.
// Tile M=64 x N=128 (3 CTAs/SM target). smem arrays: 0=Ahi, 1=Alo, 2=Whi.
// sel 0/1/2: q/k/v -> fp16 (q scaled).  sel 3: fp32 dense out (A = ctx).
// ===========================================================================
#define KC 32
#define SPITCH 40
#define GM 64
#define ARR_A (GM*SPITCH)              // 2560 elems
#define ARR_W (128*SPITCH)             // 5120 elems
#define STG (2*ARR_A + ARR_W)          // 10240 elems per stage
#define GEMM_SMEM (2*STG*2)            // 40960 bytes

__global__ __launch_bounds__(256, 3) void hmma_gemm_kernel(
    const float* __restrict__ b0in, const float* __restrict__ b1in,
    const float* __restrict__ b2in, const float* __restrict__ b3in,
    float* __restrict__ dense_out, int sel_base)
{
    extern __shared__ __half sh[];
    int tid = threadIdx.x;
    int sel = sel_base + blockIdx.z;
    int m0 = blockIdx.y * GM, n0 = blockIdx.x * 128;

    const __half* Ahi = (sel < 3) ? g_xhi : g_chi;
    const __half* Alo = (sel < 3) ? g_xlo : g_clo;
    const __half* Whi = g_whi + ((size_t)sel << 20);
    const float* bias = sel==0 ? b0in : sel==1 ? b1in : sel==2 ? b2in : b3in;

    int wid = tid >> 5, lane = tid & 31;
    int warp_m = wid >> 2, warp_n = wid & 3;     // 2 x 4 warps, warp tile 32x32
    int gID = lane >> 2, tig = lane & 3;
    uint32_t sb = smem_u32(sh);

    float acc[2][4][4];
    #pragma unroll
    for (int mf = 0; mf < 2; mf++)
        #pragma unroll
        for (int nf = 0; nf < 4; nf++)
            #pragma unroll
            for (int c = 0; c < 4; c++) acc[mf][nf][c] = 0.0f;

    const int NK = EE / KC;   // 32

    // cp slots: Ahi 256 (64r x 4), Alo 256, W 512 (128r x 4). 4 per thread.
    auto prefetch = [&](int kt, int stage) {
        int k0 = kt * KC;
        uint32_t stg = sb + (uint32_t)stage*STG*2;
        {   // Ahi: slot tid
            int r = tid >> 2, c8 = (tid & 3) * 8;
            cp16(stg + (uint32_t)(r*SPITCH + c8)*2,
                 Ahi + (size_t)(m0+r)*EE + k0 + c8);
            // Alo: slot tid
            cp16(stg + (uint32_t)(ARR_A + r*SPITCH + c8)*2,
                 Alo + (size_t)(m0+r)*EE + k0 + c8);
        }
        #pragma unroll
        for (int j = 0; j < 2; j++) {   // W: slots tid, tid+256
            int idx = tid + j*256;
            int r = idx >> 2, c8 = (idx & 3) * 8;
            cp16(stg + (uint32_t)(2*ARR_A + r*SPITCH + c8)*2,
                 Whi + (size_t)(n0+r)*EE + k0 + c8);
        }
    };

    prefetch(0, 0);
    CP_COMMIT();

    for (int kt = 0; kt < NK; kt++) {
        int cur = kt & 1;
        if (kt + 1 < NK) { prefetch(kt+1, cur^1); CP_COMMIT(); CP_WAIT1(); }
        else             { CP_WAIT0(); }
        __syncthreads();

        const __half* s = sh + cur*STG;
        #pragma unroll
        for (int ks = 0; ks < KC/16; ks++) {
            int kc = ks*16 + 2*tig;
            uint32_t bh[4][2];
            #pragma unroll
            for (int nf = 0; nf < 4; nf++) {
                int n = warp_n*32 + nf*8 + gID;
                bh[nf][0] = *(const uint32_t*)&s[2*ARR_A + n*SPITCH + kc];
                bh[nf][1] = *(const uint32_t*)&s[2*ARR_A + n*SPITCH + kc + 8];
            }
            #pragma unroll
            for (int mf = 0; mf < 2; mf++) {
                int r = warp_m*32 + mf*16 + gID;
                uint32_t ah0 = *(const uint32_t*)&s[r*SPITCH + kc];
                uint32_t ah1 = *(const uint32_t*)&s[(r+8)*SPITCH + kc];
                uint32_t ah2 = *(const uint32_t*)&s[r*SPITCH + kc + 8];
                uint32_t ah3 = *(const uint32_t*)&s[(r+8)*SPITCH + kc + 8];
                uint32_t al0 = *(const uint32_t*)&s[ARR_A + r*SPITCH + kc];
                uint32_t al1 = *(const uint32_t*)&s[ARR_A + (r+8)*SPITCH + kc];
                uint32_t al2 = *(const uint32_t*)&s[ARR_A + r*SPITCH + kc + 8];
                uint32_t al3 = *(const uint32_t*)&s[ARR_A + (r+8)*SPITCH + kc + 8];
                #pragma unroll
                for (int nf = 0; nf < 4; nf++) {
                    hmma16816(acc[mf][nf], ah0, ah1, ah2, ah3, bh[nf][0], bh[nf][1]);
                    hmma16816(acc[mf][nf], al0, al1, al2, al3, bh[nf][0], bh[nf][1]);
                }
            }
        }
        __syncthreads();
    }

    float scale = (sel == 0) ? 0.125f : 1.0f;
    #pragma unroll
    for (int mf = 0; mf < 2; mf++) {
        int m = m0 + warp_m*32 + mf*16 + gID;
        #pragma unroll
        for (int nf = 0; nf < 4; nf++) {
            int n = n0 + warp_n*32 + nf*8 + 2*tig;
            float bx = bias[n], by = bias[n+1];
            float v0 = (acc[mf][nf][0] + bx)*scale, v1 = (acc[mf][nf][1] + by)*scale;
            float v2 = (acc[mf][nf][2] + bx)*scale, v3 = (acc[mf][nf][3] + by)*scale;
            if (sel < 3) {
                int h = n >> 6, d = n & 63;
                int b1 = m >> 11, t1 = m & (TT-1);
                int m2 = m + 8;
                int b2 = m2 >> 11, t2 = m2 & (TT-1);
                size_t o1 = (((size_t)(b1*HH + h))*TT + t1)*DD + d;
                size_t o2 = (((size_t)(b2*HH + h))*TT + t2)*DD + d;
                __half* dst = (sel == 0) ? g_qh : (sel == 1) ? g_kh : g_vh;
                *(uint32_t*)&dst[o1] = packh2(v0, v1);
                *(uint32_t*)&dst[o2] = packh2(v2, v3);
            } else {
                *(float2*)&dense_out[(size_t)m*EE + n] = make_float2(v0, v1);
                *(float2*)&dense_out[(size_t)(m+8)*EE + n] = make_float2(v2, v3);
            }
        }
    }
}

// ===========================================================================
// HMMA flash attention (R15 verbatim): QK 1-pass, PV 1-pass fp16,
// online-max softmax, cp.async 2-stage, KV chunk 64.
// ===========================================================================
#define AT_KP 72
#define AT_TILE (64*AT_KP)
#define AT_STG (2*AT_TILE)
#define ATTN_SMEM (2*AT_STG*2 + 2*192*4)

__global__ __launch_bounds__(256, 2) void attn_mma_kernel()
{
    extern __shared__ __half ash[];
    float* bias_s = (float*)(ash + 2*AT_STG);    // [2][192]

    int tid = threadIdx.x;
    int wid = tid >> 5, lane = tid & 31;
    int gID = lane >> 2, tig = lane & 3;
    int bh = blockIdx.y;
    int b = bh >> 4, h = bh & 15;
    int t0 = blockIdx.x * 128;

    const __half* qh = g_qh + ((size_t)bh*TT + t0)*DD;
    const __half* kh = g_kh + (size_t)bh*TT*DD;
    const __half* vh = g_vh + (size_t)bh*TT*DD;

    uint32_t qah[4][4];
    int qr0 = wid*16 + gID;
    #pragma unroll
    for (int ks = 0; ks < 4; ks++) {
        qah[ks][0] = *(const uint32_t*)&qh[(size_t)qr0*DD + ks*16 + 2*tig];
        qah[ks][1] = *(const uint32_t*)&qh[(size_t)(qr0+8)*DD + ks*16 + 2*tig];
        qah[ks][2] = *(const uint32_t*)&qh[(size_t)qr0*DD + ks*16 + 8 + 2*tig];
        qah[ks][3] = *(const uint32_t*)&qh[(size_t)(qr0+8)*DD + ks*16 + 8 + 2*tig];
    }
    float g0_ = g_gate[(size_t)bh*TT + t0 + wid*16 + gID];
    float g1_ = g_gate[(size_t)bh*TT + t0 + wid*16 + gID + 8];

    float m0 = -1e30f, m1 = -1e30f, l0 = 0.0f, l1 = 0.0f;
    float oa[8][4];
    #pragma unroll
    for (int nf = 0; nf < 8; nf++)
        #pragma unroll
        for (int c = 0; c < 4; c++) oa[nf][c] = 0.0f;

    uint32_t sb = smem_u32(ash);

    auto loadKV = [&](int s0, int stage) {
        uint32_t stg = sb + (uint32_t)stage*AT_STG*2;
        #pragma unroll
        for (int j = 0; j < 4; j++) {
            int idx = tid + j*256;
            int a = idx >> 9;
            int c = idx & 511;
            int r = c >> 3, c8 = (c & 7)*8;
            size_t go = (size_t)(s0+r)*DD + c8;
            const __half* src = (a==0) ? kh+go : vh+go;
            cp16(stg + (uint32_t)(a*AT_TILE + r*AT_KP + c8)*2, src);
        }
    };

    const int NC = TT/64;
    loadKV(0, 0);
    CP_COMMIT();

    for (int ch = 0; ch < NC; ch++) {
        int cur = ch & 1;
        int s0 = ch * 64;
        if (ch + 1 < NC) { loadKV(s0 + 64, cur^1); CP_COMMIT(); CP_WAIT1(); }
        else             { CP_WAIT0(); }
        if (tid < 191)
            bias_s[cur*192 + tid] = g_bias[(size_t)(s0 - t0 - 127 + tid + TT - 1)*HH + h];
        __syncthreads();

        uint32_t kh_b = sb + (uint32_t)(cur*AT_STG)*2;
        uint32_t vh_b = kh_b + AT_TILE*2;
        const float* bw = bias_s + cur*192;

        float sc[8][4];
        #pragma unroll
        for (int nf = 0; nf < 8; nf++)
            #pragma unroll
            for (int c = 0; c < 4; c++) sc[nf][c] = 0.0f;

        #pragma unroll
        for (int ks = 0; ks < 4; ks++) {
            #pragma unroll
            for (int np = 0; np < 4; np++) {
                uint32_t rowoff = (((np*16 + ((lane>>4)<<3) + (lane&7))*AT_KP) + ks*16 + (((lane>>3)&1)<<3))*2;
                uint32_t rh0, rh1, rh2, rh3;
                asm volatile("ldmatrix.sync.aligned.m8n8.x4.shared.b16 {%0,%1,%2,%3}, [%4];"
                             : "=r"(rh0), "=r"(rh1), "=r"(rh2), "=r"(rh3) : "r"(kh_b + rowoff));
                hmma16816(sc[2*np],   qah[ks][0], qah[ks][1], qah[ks][2], qah[ks][3], rh0, rh1);
                hmma16816(sc[2*np+1], qah[ks][0], qah[ks][1], qah[ks][2], qah[ks][3], rh2, rh3);
            }
        }

        float mx0 = -1e30f, mx1 = -1e30f;
        #pragma unroll
        for (int nf = 0; nf < 8; nf++) {
            int u = nf*8 + 2*tig - (wid*16 + gID) + 127;
            sc[nf][0] = fmaf(g0_, bw[u],   sc[nf][0]);
            sc[nf][1] = fmaf(g0_, bw[u+1], sc[nf][1]);
            sc[nf][2] = fmaf(g1_, bw[u-8], sc[nf][2]);
            sc[nf][3] = fmaf(g1_, bw[u-7], sc[nf][3]);
            mx0 = fmaxf(mx0, fmaxf(sc[nf][0], sc[nf][1]));
            mx1 = fmaxf(mx1, fmaxf(sc[nf][2], sc[nf][3]));
        }
        mx0 = fmaxf(mx0, __shfl_xor_sync(0xffffffffu, mx0, 1));
        mx0 = fmaxf(mx0, __shfl_xor_sync(0xffffffffu, mx0, 2));
        mx1 = fmaxf(mx1, __shfl_xor_sync(0xffffffffu, mx1, 1));
        mx1 = fmaxf(mx1, __shfl_xor_sync(0xffffffffu, mx1, 2));

        float mn0 = fmaxf(m0, mx0), mn1 = fmaxf(m1, mx1);
        float al0 = fexp(m0 - mn0), al1 = fexp(m1 - mn1);
        l0 *= al0;  l1 *= al1;
        #pragma unroll
        for (int nf = 0; nf < 8; nf++) {
            sc[nf][0] = fexp(sc[nf][0] - mn0); l0 += sc[nf][0];
            sc[nf][1] = fexp(sc[nf][1] - mn0); l0 += sc[nf][1];
            sc[nf][2] = fexp(sc[nf][2] - mn1); l1 += sc[nf][2];
            sc[nf][3] = fexp(sc[nf][3] - mn1); l1 += sc[nf][3];
        }
        m0 = mn0;  m1 = mn1;
        #pragma unroll
        for (int nf = 0; nf < 8; nf++) {
            oa[nf][0] *= al0; oa[nf][1] *= al0;
            oa[nf][2] *= al1; oa[nf][3] *= al1;
        }

        #pragma unroll
        for (int ksp = 0; ksp < 4; ksp++) {
            uint32_t pa0 = packh2(sc[2*ksp][0],   sc[2*ksp][1]);
            uint32_t pa1 = packh2(sc[2*ksp][2],   sc[2*ksp][3]);
            uint32_t pa2 = packh2(sc[2*ksp+1][0], sc[2*ksp+1][1]);
            uint32_t pa3 = packh2(sc[2*ksp+1][2], sc[2*ksp+1][3]);
            #pragma unroll
            for (int np = 0; np < 4; np++) {
                uint32_t rowoff = (((16*ksp + (lane&15))*AT_KP) + np*16 + ((lane>>4)<<3))*2;
                uint32_t rh0, rh1, rh2, rh3;
                asm volatile("ldmatrix.sync.aligned.m8n8.x4.trans.shared.b16 {%0,%1,%2,%3}, [%4];"
                             : "=r"(rh0), "=r"(rh1), "=r"(rh2), "=r"(rh3) : "r"(vh_b + rowoff));
                hmma16816(oa[2*np],   pa0, pa1, pa2, pa3, rh0, rh1);
                hmma16816(oa[2*np+1], pa0, pa1, pa2, pa3, rh2, rh3);
            }
        }
        __syncthreads();
    }

    l0 += __shfl_xor_sync(0xffffffffu, l0, 1);
    l0 += __shfl_xor_sync(0xffffffffu, l0, 2);
    l1 += __shfl_xor_sync(0xffffffffu, l1, 1);
    l1 += __shfl_xor_sync(0xffffffffu, l1, 2);
    float inv0 = 1.0f / l0, inv1 = 1.0f / l1;
    int t = t0 + wid*16 + gID;
    #pragma unroll
    for (int nf = 0; nf < 8; nf++) {
        int d = nf*8 + 2*tig;
        uint32_t h0, l0p, h1, l1p;
        splith2(oa[nf][0]*inv0, oa[nf][1]*inv0, h0, l0p);
        splith2(oa[nf][2]*inv1, oa[nf][3]*inv1, h1, l1p);
        size_t o0 = ((size_t)(b*TT + t))*EE + h*DD + d;
        size_t o1 = ((size_t)(b*TT + t + 8))*EE + h*DD + d;
        *(uint32_t*)&g_chi[o0] = h0;
        *(uint32_t*)&g_chi[o1] = h1;
        *(uint32_t*)&g_clo[o0] = l0p;
        *(uint32_t*)&g_clo[o1] = l1p;
    }
}

// ---------------------------------------------------------------------------
extern "C" void kernel_launch(void* const* d_in, const int* in_sizes, int n_in,
                              void* d_out, int out_size)
{
    const float* hidden    = (const float*)d_in[0];
    const float* q_w       = (const float*)d_in[1];
    const float* q_b       = (const float*)d_in[2];
    const float* k_w       = (const float*)d_in[3];
    const float* k_b       = (const float*)d_in[4];
    const float* v_w       = (const float*)d_in[5];
    const float* v_b       = (const float*)d_in[6];
    const float* out_w     = (const float*)d_in[7];
    const float* out_b     = (const float*)d_in[8];
    const float* rel_embed = (const float*)d_in[9];
    const float* gru_const = (const float*)d_in[10];
    const float* gru_w     = (const float*)d_in[11];
    const float* gru_b     = (const float*)d_in[12];
    float* out = (float*)d_out;

    prep_kernel<<<PREP_BLOCKS, 256>>>(hidden, q_w, k_w, v_w, out_w,
                                      gru_w, gru_b, gru_const, rel_embed);

    cudaFuncSetAttribute(hmma_gemm_kernel, cudaFuncAttributeMaxDynamicSharedMemorySize, GEMM_SMEM);
    hmma_gemm_kernel<<<dim3(EE/128, BT/GM, 3), 256, GEMM_SMEM>>>(q_b, k_b, v_b, out_b, out, 0);

    cudaFuncSetAttribute(attn_mma_kernel, cudaFuncAttributeMaxDynamicSharedMemorySize, ATTN_SMEM);
    attn_mma_kernel<<<dim3(TT/128, BB*HH), 256, ATTN_SMEM>>>();

    hmma_gemm_kernel<<<dim3(EE/128, BT/GM, 1), 256, GEMM_SMEM>>>(q_b, k_b, v_b, out_b, out, 3);
}

// round 17
// speedup vs baseline: 1.5575x; 1.5575x over previous
#include <cuda_runtime.h>
#include <cuda_fp16.h>
#include <math.h>
#include <stdint.h>

#define BB 2
#define TT 2048
#define EE 1024
#define HH 16
#define DD 64
#define BT (BB*TT)            // 4096
#define BIAS_LEN (2*TT-1)     // 4095

// Scratch (device globals)
__device__ float g_gate[BB*HH*TT];
__device__ float g_bias[BIAS_LEN*HH];
__device__ __half g_qh[BB*HH*TT*DD];
__device__ __half g_kh[BB*HH*TT*DD];
__device__ __half g_vh[BB*HH*TT*DD];
__device__ __half g_xhi[BT*EE], g_xlo[BT*EE];
__device__ __half g_whi[4*EE*EE];
__device__ __half g_chi[BT*EE], g_clo[BT*EE];

// ===========================================================================
// helpers
// ===========================================================================
__device__ __forceinline__ uint32_t smem_u32(const void* p) {
    uint32_t a;
    asm("{ .reg .u64 t; cvta.to.shared.u64 t, %1; cvt.u32.u64 %0, t; }" : "=r"(a) : "l"(p));
    return a;
}
__device__ __forceinline__ void cp16(uint32_t dst, const void* src) {
    asm volatile("cp.async.ca.shared.global [%0], [%1], 16;" :: "r"(dst), "l"(src));
}
#define CP_COMMIT() asm volatile("cp.async.commit_group;" ::: "memory")
#define CP_WAIT1()  asm volatile("cp.async.wait_group 1;" ::: "memory")
#define CP_WAIT0()  asm volatile("cp.async.wait_group 0;" ::: "memory")

__device__ __forceinline__ void hmma16816(float c[4],
                                          uint32_t a0, uint32_t a1, uint32_t a2, uint32_t a3,
                                          uint32_t b0, uint32_t b1)
{
    asm volatile(
        "mma.sync.aligned.m16n8k16.row.col.f32.f16.f16.f32 "
        "{%0,%1,%2,%3}, {%4,%5,%6,%7}, {%8,%9}, {%0,%1,%2,%3};"
        : "+f"(c[0]), "+f"(c[1]), "+f"(c[2]), "+f"(c[3])
        : "r"(a0), "r"(a1), "r"(a2), "r"(a3), "r"(b0), "r"(b1));
}
// FMA-pipe exp (no MUFU); args <= 0 (online-max softmax)
__device__ __forceinline__ float fexp(float x) {
    x = fmaxf(x, -80.0f);
    float z = fmaf(x, 1.4426950408889634f, 12582912.0f);
    int n = __float_as_int(z) - 0x4B400000;
    float r = z - 12582912.0f;
    float f = fmaf(r, -0.6931471805599453f, x);
    float p = fmaf(f, 0.008333333f, 0.041666666f);
    p = fmaf(f, p, 0.16666667f);
    p = fmaf(f, p, 0.5f);
    p = fmaf(f, p, 1.0f);
    p = fmaf(f, p, 1.0f);
    return __int_as_float(__float_as_int(p) + (n << 23));
}
__device__ __forceinline__ uint32_t packh2(float a, float b) {
    __half2 t = __floats2half2_rn(a, b);
    return *(uint32_t*)&t;
}
__device__ __forceinline__ void splith2(float a, float b, uint32_t& hi, uint32_t& lo) {
    __half ha = __float2half_rn(a), hb = __float2half_rn(b);
    __half2 t{ha, hb};
    hi = *(uint32_t*)&t;
    lo = packh2(a - __half2float(ha), b - __half2float(hb));
}

// ===========================================================================
// Fused prep: conv_x | conv_w (hi only) | gate | bias_table
// ===========================================================================
#define PREP_CX 4096
#define PREP_CW 4096
#define PREP_GT 256
#define PREP_BT 16
#define PREP_BLOCKS (PREP_CX + PREP_CW + PREP_GT + PREP_BT)

__global__ __launch_bounds__(256) void prep_kernel(
    const float* __restrict__ hidden,
    const float* __restrict__ w0, const float* __restrict__ w1,
    const float* __restrict__ w2, const float* __restrict__ w3,
    const float* __restrict__ gru_w, const float* __restrict__ gru_b,
    const float* __restrict__ gru_const,
    const float* __restrict__ rel_embed)
{
    int bx = blockIdx.x;
    int tid = threadIdx.x;

    if (bx < PREP_CX) {
        int i = (bx * 256 + tid) * 4;
        float4 v = *(const float4*)&hidden[i];
        uint32_t h01, l01, h23, l23;
        splith2(v.x, v.y, h01, l01);
        splith2(v.z, v.w, h23, l23);
        *(uint2*)&g_xhi[i] = make_uint2(h01, h23);
        *(uint2*)&g_xlo[i] = make_uint2(l01, l23);
        return;
    }
    bx -= PREP_CX;
    if (bx < PREP_CW) {
        int i = (bx * 256 + tid) * 4;
        int sel = i >> 20;
        const float* src = sel==0 ? w0 : sel==1 ? w1 : sel==2 ? w2 : w3;
        float4 v = *(const float4*)&src[i & ((1<<20)-1)];
        uint32_t h01 = packh2(v.x, v.y);
        uint32_t h23 = packh2(v.z, v.w);
        *(uint2*)&g_whi[i] = make_uint2(h01, h23);
        return;
    }
    bx -= PREP_CW;
    if (bx < PREP_GT) {
        __shared__ float sw[8*DD];
        __shared__ float sb[8];
        __shared__ float scs[HH];
        for (int i = tid; i < 8*DD; i += 256) sw[i] = gru_w[i];
        if (tid < 8)  sb[tid] = gru_b[tid];
        if (tid < HH) scs[tid] = gru_const[tid];
        __syncthreads();

        int i = bx * 256 + tid;       // full 65536 coverage
        int h  = i % HH;
        int bt = i / HH;
        const float* x = hidden + (size_t)bt*EE + h*DD;
        float p[8];
        #pragma unroll
        for (int j = 0; j < 8; j++) p[j] = sb[j];
        #pragma unroll
        for (int d = 0; d < DD; d += 4) {
            float4 xv = *(const float4*)&x[d];
            #pragma unroll
            for (int j = 0; j < 8; j++) {
                p[j] += xv.x*sw[j*DD+d] + xv.y*sw[j*DD+d+1]
                      + xv.z*sw[j*DD+d+2] + xv.w*sw[j*DD+d+3];
            }
        }
        float pa = p[0]+p[1]+p[2]+p[3];
        float pb = p[4]+p[5]+p[6]+p[7];
        float ga = 1.0f/(1.0f + __expf(-pa));
        float gb = 1.0f/(1.0f + __expf(-pb));
        float gout = ga*(gb*scs[h] - 1.0f) + 2.0f;
        int b = bt / TT, t = bt % TT;
        g_gate[(b*HH + h)*TT + t] = gout;
        return;
    }
    bx -= PREP_GT;
    {
        int idx = bx * 256 + tid;
        if (idx >= BIAS_LEN) return;
        int delta = idx - (TT - 1);
        const int nb = 160;
        const int max_exact = 80;
        int rb = (delta > 0) ? nb : 0;
        int rel = abs(delta);
        int v;
        if (rel < max_exact) {
            v = rel;
        } else {
            float rf = (float)(rel < 1 ? 1 : rel);
            float large = logf(rf * (1.0f/80.0f)) * (float)(80.0 / 2.302585092994045684);
            int li = (int)((float)max_exact + large);
            v = li < (nb - 1) ? li : (nb - 1);
        }
        int bucket = rb + v;
        #pragma unroll
        for (int h = 0; h < HH; h++)
            g_bias[idx*HH + h] = rel_embed[bucket*HH + h];
    }
}

// ===========================================================================
// HMMA GEMM (R14-measured-best config): fp16 2-pass (A hi/lo, W fp16),
// cp.async 2-stage, KC=32, tile 128x128. smem arrays: 0=Ahi, 1=Alo, 2=Whi.
// sel 0/1/2: q/k/v -> fp16 (q scaled).  sel 3: fp32 dense out (A = ctx).
// ===========================================================================
#define KC 32
#define SPITCH 40
#define ARR (128*SPITCH)
#define STG (3*ARR)
#define GEMM_SMEM (2*STG*2)

__global__ __launch_bounds__(256, 2) void hmma_gemm_kernel(
    const float* __restrict__ b0in, const float* __restrict__ b1in,
    const float* __restrict__ b2in, const float* __restrict__ b3in,
    float* __restrict__ dense_out, int sel_base)
{
    extern __shared__ __half sh[];
    int tid = threadIdx.x;
    int sel = sel_base + blockIdx.z;
    int m0 = blockIdx.y * 128, n0 = blockIdx.x * 128;

    const __half* Ahi = (sel < 3) ? g_xhi : g_chi;
    const __half* Alo = (sel < 3) ? g_xlo : g_clo;
    const __half* Whi = g_whi + ((size_t)sel << 20);
    const float* bias = sel==0 ? b0in : sel==1 ? b1in : sel==2 ? b2in : b3in;

    int wid = tid >> 5, lane = tid & 31;
    int warp_m = wid >> 2, warp_n = wid & 3;
    int gID = lane >> 2, tig = lane & 3;
    uint32_t sb = smem_u32(sh);

    int cp_arr[6], cp_r[6], cp_c8[6];
    #pragma unroll
    for (int j = 0; j < 6; j++) {
        int idx = tid + j*256;
        cp_arr[j] = idx >> 9;
        int c = idx & 511;
        cp_r[j] = c >> 2;
        cp_c8[j] = (c & 3) * 8;
    }

    float acc[4][4][4];
    #pragma unroll
    for (int mf = 0; mf < 4; mf++)
        #pragma unroll
        for (int nf = 0; nf < 4; nf++)
            #pragma unroll
            for (int c = 0; c < 4; c++) acc[mf][nf][c] = 0.0f;

    const int NK = EE / KC;

    auto prefetch = [&](int kt, int stage) {
        int k0 = kt * KC;
        uint32_t stg = sb + (uint32_t)stage*STG*2;
        #pragma unroll
        for (int j = 0; j < 6; j++) {
            int a = cp_arr[j], r = cp_r[j], c8 = cp_c8[j];
            const __half* src =
                (a == 0) ? (Ahi + (size_t)(m0+r)*EE + k0 + c8) :
                (a == 1) ? (Alo + (size_t)(m0+r)*EE + k0 + c8) :
                           (Whi + (size_t)(n0+r)*EE + k0 + c8);
            cp16(stg + (uint32_t)(a*ARR + r*SPITCH + c8)*2, src);
        }
    };

    prefetch(0, 0);
    CP_COMMIT();

    for (int kt = 0; kt < NK; kt++) {
        int cur = kt & 1;
        if (kt + 1 < NK) { prefetch(kt+1, cur^1); CP_COMMIT(); CP_WAIT1(); }
        else             { CP_WAIT0(); }
        __syncthreads();

        const __half* s = sh + cur*STG;
        #pragma unroll
        for (int ks = 0; ks < KC/16; ks++) {
            int kc = ks*16 + 2*tig;
            uint32_t bh[4][2];
            #pragma unroll
            for (int nf = 0; nf < 4; nf++) {
                int n = warp_n*32 + nf*8 + gID;
                bh[nf][0] = *(const uint32_t*)&s[2*ARR + n*SPITCH + kc];
                bh[nf][1] = *(const uint32_t*)&s[2*ARR + n*SPITCH + kc + 8];
            }
            #pragma unroll
            for (int mf = 0; mf < 4; mf++) {
                int r = warp_m*64 + mf*16 + gID;
                uint32_t ah0 = *(const uint32_t*)&s[r*SPITCH + kc];
                uint32_t ah1 = *(const uint32_t*)&s[(r+8)*SPITCH + kc];
                uint32_t ah2 = *(const uint32_t*)&s[r*SPITCH + kc + 8];
                uint32_t ah3 = *(const uint32_t*)&s[(r+8)*SPITCH + kc + 8];
                uint32_t al0 = *(const uint32_t*)&s[ARR + r*SPITCH + kc];
                uint32_t al1 = *(const uint32_t*)&s[ARR + (r+8)*SPITCH + kc];
                uint32_t al2 = *(const uint32_t*)&s[ARR + r*SPITCH + kc + 8];
                uint32_t al3 = *(const uint32_t*)&s[ARR + (r+8)*SPITCH + kc + 8];
                #pragma unroll
                for (int nf = 0; nf < 4; nf++) {
                    hmma16816(acc[mf][nf], ah0, ah1, ah2, ah3, bh[nf][0], bh[nf][1]);
                    hmma16816(acc[mf][nf], al0, al1, al2, al3, bh[nf][0], bh[nf][1]);
                }
            }
        }
        __syncthreads();
    }

    float scale = (sel == 0) ? 0.125f : 1.0f;
    #pragma unroll
    for (int mf = 0; mf < 4; mf++) {
        int m = m0 + warp_m*64 + mf*16 + gID;
        #pragma unroll
        for (int nf = 0; nf < 4; nf++) {
            int n = n0 + warp_n*32 + nf*8 + 2*tig;
            float bx = bias[n], by = bias[n+1];
            float v0 = (acc[mf][nf][0] + bx)*scale, v1 = (acc[mf][nf][1] + by)*scale;
            float v2 = (acc[mf][nf][2] + bx)*scale, v3 = (acc[mf][nf][3] + by)*scale;
            if (sel < 3) {
                int h = n >> 6, d = n & 63;
                int b1 = m >> 11, t1 = m & (TT-1);
                int m2 = m + 8;
                int b2 = m2 >> 11, t2 = m2 & (TT-1);
                size_t o1 = (((size_t)(b1*HH + h))*TT + t1)*DD + d;
                size_t o2 = (((size_t)(b2*HH + h))*TT + t2)*DD + d;
                __half* dst = (sel == 0) ? g_qh : (sel == 1) ? g_kh : g_vh;
                *(uint32_t*)&dst[o1] = packh2(v0, v1);
                *(uint32_t*)&dst[o2] = packh2(v2, v3);
            } else {
                *(float2*)&dense_out[(size_t)m*EE + n] = make_float2(v0, v1);
                *(float2*)&dense_out[(size_t)(m+8)*EE + n] = make_float2(v2, v3);
            }
        }
    }
}

// ===========================================================================
// HMMA flash attention (R15 verbatim): QK 1-pass fp16, PV 1-pass fp16,
// online-max softmax, cp.async 2-stage, KV chunk 64.
// ===========================================================================
#define AT_KP 72
#define AT_TILE (64*AT_KP)
#define AT_STG (2*AT_TILE)
#define ATTN_SMEM (2*AT_STG*2 + 2*192*4)

__global__ __launch_bounds__(256, 2) void attn_mma_kernel()
{
    extern __shared__ __half ash[];
    float* bias_s = (float*)(ash + 2*AT_STG);    // [2][192]

    int tid = threadIdx.x;
    int wid = tid >> 5, lane = tid & 31;
    int gID = lane >> 2, tig = lane & 3;
    int bh = blockIdx.y;
    int b = bh >> 4, h = bh & 15;
    int t0 = blockIdx.x * 128;

    const __half* qh = g_qh + ((size_t)bh*TT + t0)*DD;
    const __half* kh = g_kh + (size_t)bh*TT*DD;
    const __half* vh = g_vh + (size_t)bh*TT*DD;

    uint32_t qah[4][4];
    int qr0 = wid*16 + gID;
    #pragma unroll
    for (int ks = 0; ks < 4; ks++) {
        qah[ks][0] = *(const uint32_t*)&qh[(size_t)qr0*DD + ks*16 + 2*tig];
        qah[ks][1] = *(const uint32_t*)&qh[(size_t)(qr0+8)*DD + ks*16 + 2*tig];
        qah[ks][2] = *(const uint32_t*)&qh[(size_t)qr0*DD + ks*16 + 8 + 2*tig];
        qah[ks][3] = *(const uint32_t*)&qh[(size_t)(qr0+8)*DD + ks*16 + 8 + 2*tig];
    }
    float g0_ = g_gate[(size_t)bh*TT + t0 + wid*16 + gID];
    float g1_ = g_gate[(size_t)bh*TT + t0 + wid*16 + gID + 8];

    float m0 = -1e30f, m1 = -1e30f, l0 = 0.0f, l1 = 0.0f;
    float oa[8][4];
    #pragma unroll
    for (int nf = 0; nf < 8; nf++)
        #pragma unroll
        for (int c = 0; c < 4; c++) oa[nf][c] = 0.0f;

    uint32_t sb = smem_u32(ash);

    auto loadKV = [&](int s0, int stage) {
        uint32_t stg = sb + (uint32_t)stage*AT_STG*2;
        #pragma unroll
        for (int j = 0; j < 4; j++) {
            int idx = tid + j*256;
            int a = idx >> 9;
            int c = idx & 511;
            int r = c >> 3, c8 = (c & 7)*8;
            size_t go = (size_t)(s0+r)*DD + c8;
            const __half* src = (a==0) ? kh+go : vh+go;
            cp16(stg + (uint32_t)(a*AT_TILE + r*AT_KP + c8)*2, src);
        }
    };

    const int NC = TT/64;
    loadKV(0, 0);
    CP_COMMIT();

    for (int ch = 0; ch < NC; ch++) {
        int cur = ch & 1;
        int s0 = ch * 64;
        if (ch + 1 < NC) { loadKV(s0 + 64, cur^1); CP_COMMIT(); CP_WAIT1(); }
        else             { CP_WAIT0(); }
        if (tid < 191)
            bias_s[cur*192 + tid] = g_bias[(size_t)(s0 - t0 - 127 + tid + TT - 1)*HH + h];
        __syncthreads();

        uint32_t kh_b = sb + (uint32_t)(cur*AT_STG)*2;
        uint32_t vh_b = kh_b + AT_TILE*2;
        const float* bw = bias_s + cur*192;

        // ---- S = Q K^T, 1-pass fp16
        float sc[8][4];
        #pragma unroll
        for (int nf = 0; nf < 8; nf++)
            #pragma unroll
            for (int c = 0; c < 4; c++) sc[nf][c] = 0.0f;

        #pragma unroll
        for (int ks = 0; ks < 4; ks++) {
            #pragma unroll
            for (int np = 0; np < 4; np++) {
                uint32_t rowoff = (((np*16 + ((lane>>4)<<3) + (lane&7))*AT_KP) + ks*16 + (((lane>>3)&1)<<3))*2;
                uint32_t rh0, rh1, rh2, rh3;
                asm volatile("ldmatrix.sync.aligned.m8n8.x4.shared.b16 {%0,%1,%2,%3}, [%4];"
                             : "=r"(rh0), "=r"(rh1), "=r"(rh2), "=r"(rh3) : "r"(kh_b + rowoff));
                hmma16816(sc[2*np],   qah[ks][0], qah[ks][1], qah[ks][2], qah[ks][3], rh0, rh1);
                hmma16816(sc[2*np+1], qah[ks][0], qah[ks][1], qah[ks][2], qah[ks][3], rh2, rh3);
            }
        }

        // ---- bias + online-max softmax
        float mx0 = -1e30f, mx1 = -1e30f;
        #pragma unroll
        for (int nf = 0; nf < 8; nf++) {
            int u = nf*8 + 2*tig - (wid*16 + gID) + 127;
            sc[nf][0] = fmaf(g0_, bw[u],   sc[nf][0]);
            sc[nf][1] = fmaf(g0_, bw[u+1], sc[nf][1]);
            sc[nf][2] = fmaf(g1_, bw[u-8], sc[nf][2]);
            sc[nf][3] = fmaf(g1_, bw[u-7], sc[nf][3]);
            mx0 = fmaxf(mx0, fmaxf(sc[nf][0], sc[nf][1]));
            mx1 = fmaxf(mx1, fmaxf(sc[nf][2], sc[nf][3]));
        }
        mx0 = fmaxf(mx0, __shfl_xor_sync(0xffffffffu, mx0, 1));
        mx0 = fmaxf(mx0, __shfl_xor_sync(0xffffffffu, mx0, 2));
        mx1 = fmaxf(mx1, __shfl_xor_sync(0xffffffffu, mx1, 1));
        mx1 = fmaxf(mx1, __shfl_xor_sync(0xffffffffu, mx1, 2));

        float mn0 = fmaxf(m0, mx0), mn1 = fmaxf(m1, mx1);
        float al0 = fexp(m0 - mn0), al1 = fexp(m1 - mn1);
        l0 *= al0;  l1 *= al1;
        #pragma unroll
        for (int nf = 0; nf < 8; nf++) {
            sc[nf][0] = fexp(sc[nf][0] - mn0); l0 += sc[nf][0];
            sc[nf][1] = fexp(sc[nf][1] - mn0); l0 += sc[nf][1];
            sc[nf][2] = fexp(sc[nf][2] - mn1); l1 += sc[nf][2];
            sc[nf][3] = fexp(sc[nf][3] - mn1); l1 += sc[nf][3];
        }
        m0 = mn0;  m1 = mn1;
        #pragma unroll
        for (int nf = 0; nf < 8; nf++) {
            oa[nf][0] *= al0; oa[nf][1] *= al0;
            oa[nf][2] *= al1; oa[nf][3] *= al1;
        }

        // ---- O += P V, 1-pass fp16
        #pragma unroll
        for (int ksp = 0; ksp < 4; ksp++) {
            uint32_t pa0 = packh2(sc[2*ksp][0],   sc[2*ksp][1]);
            uint32_t pa1 = packh2(sc[2*ksp][2],   sc[2*ksp][3]);
            uint32_t pa2 = packh2(sc[2*ksp+1][0], sc[2*ksp+1][1]);
            uint32_t pa3 = packh2(sc[2*ksp+1][2], sc[2*ksp+1][3]);
            #pragma unroll
            for (int np = 0; np < 4; np++) {
                uint32_t rowoff = (((16*ksp + (lane&15))*AT_KP) + np*16 + ((lane>>4)<<3))*2;
                uint32_t rh0, rh1, rh2, rh3;
                asm volatile("ldmatrix.sync.aligned.m8n8.x4.trans.shared.b16 {%0,%1,%2,%3}, [%4];"
                             : "=r"(rh0), "=r"(rh1), "=r"(rh2), "=r"(rh3) : "r"(vh_b + rowoff));
                hmma16816(oa[2*np],   pa0, pa1, pa2, pa3, rh0, rh1);
                hmma16816(oa[2*np+1], pa0, pa1, pa2, pa3, rh2, rh3);
            }
        }
        __syncthreads();
    }

    l0 += __shfl_xor_sync(0xffffffffu, l0, 1);
    l0 += __shfl_xor_sync(0xffffffffu, l0, 2);
    l1 += __shfl_xor_sync(0xffffffffu, l1, 1);
    l1 += __shfl_xor_sync(0xffffffffu, l1, 2);
    float inv0 = 1.0f / l0, inv1 = 1.0f / l1;
    int t = t0 + wid*16 + gID;
    #pragma unroll
    for (int nf = 0; nf < 8; nf++) {
        int d = nf*8 + 2*tig;
        uint32_t h0, l0p, h1, l1p;
        splith2(oa[nf][0]*inv0, oa[nf][1]*inv0, h0, l0p);
        splith2(oa[nf][2]*inv1, oa[nf][3]*inv1, h1, l1p);
        size_t o0 = ((size_t)(b*TT + t))*EE + h*DD + d;
        size_t o1 = ((size_t)(b*TT + t + 8))*EE + h*DD + d;
        *(uint32_t*)&g_chi[o0] = h0;
        *(uint32_t*)&g_chi[o1] = h1;
        *(uint32_t*)&g_clo[o0] = l0p;
        *(uint32_t*)&g_clo[o1] = l1p;
    }
}

// ---------------------------------------------------------------------------
extern "C" void kernel_launch(void* const* d_in, const int* in_sizes, int n_in,
                              void* d_out, int out_size)
{
    const float* hidden    = (const float*)d_in[0];
    const float* q_w       = (const float*)d_in[1];
    const float* q_b       = (const float*)d_in[2];
    const float* k_w       = (const float*)d_in[3];
    const float* k_b       = (const float*)d_in[4];
    const float* v_w       = (const float*)d_in[5];
    const float* v_b       = (const float*)d_in[6];
    const float* out_w     = (const float*)d_in[7];
    const float* out_b     = (const float*)d_in[8];
    const float* rel_embed = (const float*)d_in[9];
    const float* gru_const = (const float*)d_in[10];
    const float* gru_w     = (const float*)d_in[11];
    const float* gru_b     = (const float*)d_in[12];
    float* out = (float*)d_out;

    prep_kernel<<<PREP_BLOCKS, 256>>>(hidden, q_w, k_w, v_w, out_w,
                                      gru_w, gru_b, gru_const, rel_embed);

    cudaFuncSetAttribute(hmma_gemm_kernel, cudaFuncAttributeMaxDynamicSharedMemorySize, GEMM_SMEM);
    hmma_gemm_kernel<<<dim3(EE/128, BT/128, 3), 256, GEMM_SMEM>>>(q_b, k_b, v_b, out_b, out, 0);

    cudaFuncSetAttribute(attn_mma_kernel, cudaFuncAttributeMaxDynamicSharedMemorySize, ATTN_SMEM);
    attn_mma_kernel<<<dim3(TT/128, BB*HH), 256, ATTN_SMEM>>>();

    hmma_gemm_kernel<<<dim3(EE/128, BT/128, 1), 256, GEMM_SMEM>>>(q_b, k_b, v_b, out_b, out, 3);
}